// round 12
// baseline (speedup 1.0000x reference)
#include <cuda_runtime.h>

// Problem constants
#define BATCH 8
#define IMH 180
#define IMW 180
#define NF 24
#define NB 31
#define NPIX (IMH * IMW)          // 32400
#define NTOT (BATCH * NPIX)       // 259200
#define N4   (NTOT / 4)           // 64800

// LUT for phi(x) = sum_j w_j exp(-50 (x-mu_j)^2), x in [XMIN, XMAX]
#define NCELL 1024
#define XMIN (-2.0f)
#define XMAX (2.0f)
#define LUT_H ((XMAX - XMIN) / (float)NCELL)
#define LUT_INVH ((float)NCELL / (XMAX - XMIN))

// Tiles: 64 wide x 32 tall, 512 threads, grid (3,6,8) = 144 CTAs
#define TW 64
#define TH 32
#define URS 72                     // smem row stride (36x68 tile padded)

// Global phi scratch: 192 planes of 200x200, "+2-shifted" layout:
//   plane[(gy+2)*200 + (gx+2)] = scaled_phi(gy, gx); border cells = 0.
#define PW 200
#define PPLANE (PW * PW)           // 40000

__device__ float  g_partials[64];
__device__ float2 g_lut[NCELL];
__device__ float  g_phi[BATCH * NF * PPLANE];   // ~30.7 MB

// ---------------------------------------------------------------------------
// k_init: blocks [0,4) LUT; [4,68) partial sums for M; [68,260) zero the
// border frame of each phi plane (cells outside [2,182)^2 — never written
// by k_phi; zero = conv zero-padding).
// ---------------------------------------------------------------------------
__global__ void k_init(const float* __restrict__ u,
                       const float* __restrict__ mu,
                       const float* __restrict__ wts) {
    const int tid = threadIdx.x;
    if (blockIdx.x < 4) {
        int i = blockIdx.x * 256 + tid;        // 0..1023
        float x0 = XMIN + (float)i * LUT_H;
        float x1 = x0 + LUT_H;
        float p0 = 0.f, p1 = 0.f;
        #pragma unroll 1
        for (int j = 0; j < NB; j++) {
            float m = mu[j], w = wts[j];
            float d0 = x0 - m, d1 = x1 - m;
            p0 += w * expf(-50.f * d0 * d0);
            p1 += w * expf(-50.f * d1 * d1);
        }
        g_lut[i] = make_float2(p0, p1 - p0);
    } else if (blockIdx.x < 68) {
        __shared__ float sm[256];
        const int pb = blockIdx.x - 4;         // 0..63
        float s = 0.f;
        for (int i = pb * 256 + tid; i < N4; i += 64 * 256) {
            int idx4 = i * 4;
            int p = idx4 % NPIX;
            int y = p / IMW;
            int x0 = p - y * IMW;
            float wy = 3.f - (y == 0 ? 1.f : 0.f) - (y == IMH - 1 ? 1.f : 0.f);
            float4 v = ((const float4*)u)[i];
            float w0 = (x0 == 0) ? 2.f : 3.f;
            float w3 = (x0 == IMW - 4) ? 2.f : 3.f;
            s += wy * (v.x * w0 + v.y * 3.f + v.z * 3.f + v.w * w3);
        }
        sm[tid] = s;
        __syncthreads();
        for (int o = 128; o > 0; o >>= 1) {
            if (tid < o) sm[tid] += sm[tid + o];
            __syncthreads();
        }
        if (tid == 0) g_partials[pb] = sm[0];
    } else {
        // border zeroing: plane p, 7600 frame cells
        const int p = blockIdx.x - 68;         // 0..191
        float* plane = g_phi + p * PPLANE;
        for (int i = tid; i < 7600; i += 256) {
            int r, c;
            if (i < 4000) {                    // 20 full rows (0,1,182..199)
                int j = i / PW;
                r = (j < 2) ? j : j + 180;
                c = i % PW;
            } else {                           // rows 2..181, 20 border cols
                int j = i - 4000;
                r = 2 + j / 20;
                int cc = j % 20;
                c = (cc < 2) ? cc : cc + 180;
            }
            plane[r * PW + c] = 0.f;
        }
    }
}

// ---------------------------------------------------------------------------
// k_phi: forward conv + LUT phi + (u_sigma/M) scale, written once per pixel.
// 512 threads, tile 64x32, each thread a 1x4 strip for all 24 filters.
// smem: [0,8192) LUT; [8192,18560) sU 36x72; [18560,22400) sF 24x40.
// ---------------------------------------------------------------------------
__global__ __launch_bounds__(512) void k_phi(
    const float* __restrict__ u,
    const float* __restrict__ filt)
{
    __shared__ float2 sLUT[NCELL];
    __shared__ float  sU[36 * URS];
    __shared__ float  sF[NF * 40];
    __shared__ float  s_invM;

    const int b   = blockIdx.z;
    const int oy0 = blockIdx.y * TH;
    const int ox0 = blockIdx.x * TW;
    const int tid = threadIdx.x;
    const float* ub = u + b * NPIX;

    // invM
    if (tid < 32) {
        float s = g_partials[tid] + g_partials[tid + 32];
        #pragma unroll
        for (int o = 16; o > 0; o >>= 1)
            s += __shfl_down_sync(0xffffffffu, s, o);
        if (tid == 0)
            s_invM = 1.f / (s / (9.f * (float)NTOT) + 0.001f);
    }
    // LUT
    ((float4*)sLUT)[tid] = ((const float4*)g_lut)[tid];
    // taps (stride-8 padded rows)
    if (tid < NF * 40) sF[tid] = 0.f;
    __syncthreads();
    for (int i = tid; i < NF * 25; i += 512) {
        int fi = i / 25, r25 = i - fi * 25;
        int ky = r25 / 5, kx = r25 - ky * 5;
        sF[fi * 40 + ky * 8 + kx] = filt[i];
    }
    // u tile 36 x 68 (origin oy0-2, ox0-2), zero outside image
    for (int i = tid; i < 36 * 68; i += 512) {
        int r = i / 68, c = i - r * 68;
        int gy = oy0 - 2 + r, gx = ox0 - 2 + c;
        float v = 0.f;
        if ((unsigned)gy < IMH && (unsigned)gx < IMW) v = ub[gy * IMW + gx];
        sU[r * URS + c] = v;
    }
    __syncthreads();

    const float invM = s_invM;
    const int y  = tid >> 4;               // 0..31
    const int xq = (tid & 15) * 4;         // 0..60
    const int gy = oy0 + y;

    // u_sigma/M for this strip (0 outside image -> phi written as 0)
    float us[4] = {0.f, 0.f, 0.f, 0.f};
    {
        #pragma unroll
        for (int rw = 1; rw <= 3; rw++) {
            const float4* rp = (const float4*)&sU[(y + rw) * URS + xq];
            float4 A = rp[0], B = rp[1];
            float w[8] = {A.x, A.y, A.z, A.w, B.x, B.y, B.z, B.w};
            #pragma unroll
            for (int k = 0; k < 4; k++)
                us[k] += w[k + 1] + w[k + 2] + w[k + 3];
        }
        #pragma unroll
        for (int k = 0; k < 4; k++) {
            int gx = ox0 + xq + k;
            us[k] = (gy < IMH && gx < IMW) ? us[k] * (1.f / 9.f) * invM : 0.f;
        }
    }

    float* wbase = g_phi + (b * NF) * PPLANE + (gy + 2) * PW + (ox0 + xq + 2);

    #pragma unroll 1
    for (int f = 0; f < NF; f++) {
        const float* Fp = &sF[f * 40];
        float a0 = 0.f, a1 = 0.f, a2 = 0.f, a3 = 0.f;
        #pragma unroll
        for (int ky = 0; ky < 5; ky++) {
            float4 tq = *(const float4*)&Fp[ky * 8];
            float t4v = Fp[ky * 8 + 4];
            const float4* rp = (const float4*)&sU[(y + ky) * URS + xq];
            float4 A = rp[0], B = rp[1];
            a0 = fmaf(A.x, tq.x, a0); a1 = fmaf(A.y, tq.x, a1);
            a2 = fmaf(A.z, tq.x, a2); a3 = fmaf(A.w, tq.x, a3);
            a0 = fmaf(A.y, tq.y, a0); a1 = fmaf(A.z, tq.y, a1);
            a2 = fmaf(A.w, tq.y, a2); a3 = fmaf(B.x, tq.y, a3);
            a0 = fmaf(A.z, tq.z, a0); a1 = fmaf(A.w, tq.z, a1);
            a2 = fmaf(B.x, tq.z, a2); a3 = fmaf(B.y, tq.z, a3);
            a0 = fmaf(A.w, tq.w, a0); a1 = fmaf(B.x, tq.w, a1);
            a2 = fmaf(B.y, tq.w, a2); a3 = fmaf(B.z, tq.w, a3);
            a0 = fmaf(B.x, t4v, a0); a1 = fmaf(B.y, t4v, a1);
            a2 = fmaf(B.z, t4v, a2); a3 = fmaf(B.w, t4v, a3);
        }
        float conv[4] = {a0, a1, a2, a3};
        float res[4];
        #pragma unroll
        for (int k = 0; k < 4; k++) {
            float xc = fminf(fmaxf(conv[k], XMIN), XMAX);
            float tt = (xc - XMIN) * LUT_INVH;
            int ii = (int)tt;
            ii = min(ii, NCELL - 1);
            float frac = tt - (float)ii;
            float2 cell = sLUT[ii];
            res[k] = us[k] * fmaf(cell.y, frac, cell.x);
        }
        float* wp = wbase + f * PPLANE;
        *(float2*)(wp + 0) = make_float2(res[0], res[1]);
        *(float2*)(wp + 2) = make_float2(res[2], res[3]);
    }
}

// ---------------------------------------------------------------------------
// k_adj: adjoint conv over 24 phi planes (L2 -> smem double-buffered) +
// reaction + clip. 512 threads, tile 64x32, 1x4 strip per thread.
// smem: buf0/buf1 36x72, sF 24x40.
// ---------------------------------------------------------------------------
__global__ __launch_bounds__(512) void k_adj(
    const float* __restrict__ u,
    const float* __restrict__ f,
    const float* __restrict__ filt,
    const float* __restrict__ lam,
    float* __restrict__ out)
{
    __shared__ float sB0[36 * URS];
    __shared__ float sB1[36 * URS];
    __shared__ float sF[NF * 40];

    const int b   = blockIdx.z;
    const int oy0 = blockIdx.y * TH;
    const int ox0 = blockIdx.x * TW;
    const int tid = threadIdx.x;

    if (tid < NF * 40) sF[tid] = 0.f;
    __syncthreads();
    for (int i = tid; i < NF * 25; i += 512) {
        int fi = i / 25, r25 = i - fi * 25;
        int ky = r25 / 5, kx = r25 - ky * 5;
        sF[fi * 40 + ky * 8 + kx] = filt[i];
    }

    // fixed per-thread load slots: 612 float4 per plane tile (36 rows x 17)
    const int iA = tid;                     // < 612 always
    const int iB = tid + 512;               // valid if tid < 100
    const int rA = iA / 17, cA = iA - rA * 17;
    const int rB = iB / 17, cB = iB - rB * 17;
    const long ofsA = (long)(oy0 + rA) * PW + ox0 + cA * 4;
    const long ofsB = (long)(oy0 + rB) * PW + ox0 + cB * 4;
    const float* pbase = g_phi + (long)(b * NF) * PPLANE;

    float4 pA = *(const float4*)(pbase + ofsA);
    float4 pB = (tid < 100) ? *(const float4*)(pbase + ofsB)
                            : make_float4(0.f, 0.f, 0.f, 0.f);

    const int y  = tid >> 4;                // 0..31
    const int xq = (tid & 15) * 4;          // 0..60
    float acc0 = 0.f, acc1 = 0.f, acc2 = 0.f, acc3 = 0.f;

    __syncthreads();                        // sF ready

    #pragma unroll 1
    for (int fi = 0; fi < NF; fi++) {
        float* buf = (fi & 1) ? sB1 : sB0;
        *(float4*)&buf[rA * URS + cA * 4] = pA;
        if (tid < 100) *(float4*)&buf[rB * URS + cB * 4] = pB;
        __syncthreads();
        if (fi + 1 < NF) {
            const float* pnext = pbase + (long)(fi + 1) * PPLANE;
            pA = *(const float4*)(pnext + ofsA);
            if (tid < 100) pB = *(const float4*)(pnext + ofsB);
        }
        // adjoint conv from buf, taps reversed in registers
        const float* Fp = &sF[fi * 40];
        #pragma unroll
        for (int ky = 0; ky < 5; ky++) {
            float4 tq = *(const float4*)&Fp[(4 - ky) * 8];
            float tr0 = Fp[(4 - ky) * 8 + 4];
            float tr1 = tq.w, tr2 = tq.z, tr3 = tq.y, tr4 = tq.x;
            const float4* rp = (const float4*)&buf[(y + ky) * URS + xq];
            float4 A = rp[0], B = rp[1];
            acc0 = fmaf(A.x, tr0, acc0); acc1 = fmaf(A.y, tr0, acc1);
            acc2 = fmaf(A.z, tr0, acc2); acc3 = fmaf(A.w, tr0, acc3);
            acc0 = fmaf(A.y, tr1, acc0); acc1 = fmaf(A.z, tr1, acc1);
            acc2 = fmaf(A.w, tr1, acc2); acc3 = fmaf(B.x, tr1, acc3);
            acc0 = fmaf(A.z, tr2, acc0); acc1 = fmaf(A.w, tr2, acc1);
            acc2 = fmaf(B.x, tr2, acc2); acc3 = fmaf(B.y, tr2, acc3);
            acc0 = fmaf(A.w, tr3, acc0); acc1 = fmaf(B.x, tr3, acc1);
            acc2 = fmaf(B.y, tr3, acc2); acc3 = fmaf(B.z, tr3, acc3);
            acc0 = fmaf(B.x, tr4, acc0); acc1 = fmaf(B.y, tr4, acc1);
            acc2 = fmaf(B.z, tr4, acc2); acc3 = fmaf(B.w, tr4, acc3);
        }
        __syncthreads();
    }

    // epilogue: reaction + clip
    const int gy = oy0 + y;
    const int gx0 = ox0 + xq;
    if (gy < IMH && gx0 < IMW) {
        const float lambda = lam[0];
        const float* ub = u + b * NPIX;
        const float* fb = f + b * NPIX;
        float4 uv4 = *(const float4*)&ub[gy * IMW + gx0];
        float4 fv4 = *(const float4*)&fb[gy * IMW + gx0];
        float uvs[4] = {uv4.x, uv4.y, uv4.z, uv4.w};
        float fvs[4] = {fv4.x, fv4.y, fv4.z, fv4.w};
        float accs[4] = {acc0, acc1, acc2, acc3};
        float res[4];
        #pragma unroll
        for (int k = 0; k < 4; k++) {
            float uv = uvs[k];
            float reac = lambda * (uv - fvs[k]) / (uv * uv + 1e-3f);
            float o = uv - accs[k] - reac;
            res[k] = fminf(fmaxf(o, 0.f), 1.f);
        }
        *(float4*)&(out + b * NPIX)[gy * IMW + gx0] =
            make_float4(res[0], res[1], res[2], res[3]);
    }
}

// ---------------------------------------------------------------------------
// Launch
// ---------------------------------------------------------------------------
extern "C" void kernel_launch(void* const* d_in, const int* in_sizes, int n_in,
                              void* d_out, int out_size) {
    const float* u    = (const float*)d_in[0];
    const float* f    = (const float*)d_in[1];
    const float* filt = (const float*)d_in[2];
    const float* lam  = (const float*)d_in[3];
    const float* mu   = (const float*)d_in[4];
    const float* wts  = (const float*)d_in[5];
    float* out = (float*)d_out;

    k_init<<<260, 256>>>(u, mu, wts);
    dim3 grid(3, 6, BATCH);                 // 64x32 tiles over 180x180
    k_phi<<<grid, 512>>>(u, filt);
    k_adj<<<grid, 512>>>(u, f, filt, lam, out);
}

// round 13
// speedup vs baseline: 1.1015x; 1.1015x over previous
#include <cuda_runtime.h>

// Problem constants
#define BATCH 8
#define IMH 180
#define IMW 180
#define NF 24
#define NB 31
#define NPIX (IMH * IMW)          // 32400
#define NTOT (BATCH * NPIX)       // 259200
#define N4   (NTOT / 4)           // 64800

#define TILE 32
#define UT 40                      // u tile rows/cols (TILE + 2*4)
#define SRS 68                     // sU row stride: 68/4=17 == 1 mod 8 -> identity bank map
#define PT 36                      // phi tile rows/cols (TILE + 2*2)
#define PRS 36                     // phi/US row stride: 36/4=9 == 1 mod 8 -> identity bank map

// LUT for phi(x), x in [XMIN, XMAX]; magic-number rounding index, centered slope
#define NCELL 1024
#define XMIN (-2.0f)
#define XMAX (2.0f)
#define LUT_H ((XMAX - XMIN) / (float)NCELL)
#define LUT_INVH ((float)NCELL / (XMAX - XMIN))
#define MAGICF 12582912.0f         // 1.5 * 2^23
#define MAGICI 0x4B400000

#define NTHR 512                   // 2 filter-groups of 256 threads
#define NFG  12                    // filters per group (6 pairs)

__device__ float  g_partials[64];
__device__ float2 g_lut[NCELL];

// ---------------------------------------------------------------------------
// k_init: blocks [0,4) build the LUT (value at knot, centered slope);
// blocks [4,68) weighted partial sums for M.
// ---------------------------------------------------------------------------
__global__ void k_init(const float* __restrict__ u,
                       const float* __restrict__ mu,
                       const float* __restrict__ wts) {
    const int tid = threadIdx.x;
    if (blockIdx.x < 4) {
        int i = blockIdx.x * 256 + tid;        // 0..1023
        float xc = XMIN + (float)i * LUT_H;
        float pm = 0.f, p0 = 0.f, pp = 0.f;
        #pragma unroll 1
        for (int j = 0; j < NB; j++) {
            float m = mu[j], w = wts[j];
            float dm = xc - LUT_H - m, d0 = xc - m, dp = xc + LUT_H - m;
            pm += w * expf(-50.f * dm * dm);
            p0 += w * expf(-50.f * d0 * d0);
            pp += w * expf(-50.f * dp * dp);
        }
        g_lut[i] = make_float2(p0, 0.5f * (pp - pm));
    } else {
        __shared__ float sm[256];
        const int pb = blockIdx.x - 4;         // 0..63
        float s = 0.f;
        for (int i = pb * 256 + tid; i < N4; i += 64 * 256) {
            int idx4 = i * 4;
            int p = idx4 % NPIX;
            int y = p / IMW;
            int x0 = p - y * IMW;
            float wy = 3.f - (y == 0 ? 1.f : 0.f) - (y == IMH - 1 ? 1.f : 0.f);
            float4 v = ((const float4*)u)[i];
            float w0 = (x0 == 0) ? 2.f : 3.f;
            float w3 = (x0 == IMW - 4) ? 2.f : 3.f;
            s += wy * (v.x * w0 + v.y * 3.f + v.z * 3.f + v.w * w3);
        }
        sm[tid] = s;
        __syncthreads();
        for (int o = 128; o > 0; o >>= 1) {
            if (tid < o) sm[tid] += sm[tid + o];
            __syncthreads();
        }
        if (tid == 0) g_partials[pb] = sm[0];
    }
}

// ---------------------------------------------------------------------------
// k_main: fused TNRD stage per 32x32 tile; 2 filter-groups of 256 threads.
// Pair-filter forward (one row-load feeds 2 filters), 4 phi buffers/group,
// pipeline FWDpair(p) || ADJ(pair p-1), 1 named barrier per pair.
// Dynamic smem layout (bytes):
//   [0, 8192)        sLUT : 1024 x float2
//   [8192, 19072)    sU   : 40 rows x 68 stride
//   [19072, 24256)   sUS  : 36 rows x 36 stride
//   [24256, 65728)   sPhi : 8 buffers of 36x36 (4 per group)
//   [65728, 69568)   sF   : 24 filters x 5 rows x 8 floats (padded)
// ---------------------------------------------------------------------------
#define OFF_LUT 0
#define OFF_U   8192
#define OFF_US  19072
#define OFF_PHI 24256
#define OFF_F   65728
#define PHI_STRIDE (PT * PRS * 4)  // 5184 bytes
#define SMEM_BYTES 69568

__global__ __launch_bounds__(NTHR, 2) void k_main(
    const float* __restrict__ u,
    const float* __restrict__ f,
    const float* __restrict__ filt,
    const float* __restrict__ lam,
    float* __restrict__ out)
{
    extern __shared__ char smem[];
    float2* sLUT = (float2*)(smem + OFF_LUT);
    float*  sU   = (float*)(smem + OFF_U);
    float*  sUS  = (float*)(smem + OFF_US);
    float*  sF   = (float*)(smem + OFF_F);
    __shared__ float s_invM;

    const int b   = blockIdx.z;
    const int oy0 = blockIdx.y * TILE;
    const int ox0 = blockIdx.x * TILE;
    const int tid = threadIdx.x;
    const int g   = tid >> 8;          // filter-group 0/1
    const int gt  = tid & 255;         // lane within group

    const float* ub = u + b * NPIX;
    const float* fb = f + b * NPIX;
    float* ob = out + b * NPIX;

    float* pb0 = (float*)(smem + OFF_PHI + (4 * g + 0) * PHI_STRIDE);
    float* pb1 = (float*)(smem + OFF_PHI + (4 * g + 1) * PHI_STRIDE);
    float* pb2 = (float*)(smem + OFF_PHI + (4 * g + 2) * PHI_STRIDE);
    float* pb3 = (float*)(smem + OFF_PHI + (4 * g + 3) * PHI_STRIDE);

    // ---- invM: single-warp shuffle reduction over 64 partials ----
    if (tid < 32) {
        float s = g_partials[tid] + g_partials[tid + 32];
        #pragma unroll
        for (int o = 16; o > 0; o >>= 1)
            s += __shfl_down_sync(0xffffffffu, s, o);
        if (tid == 0)
            s_invM = 1.f / (s / (9.f * (float)NTOT) + 0.001f);
    }

    // ---- cooperative loads ----
    ((float4*)sLUT)[tid] = ((const float4*)g_lut)[tid];   // 512 float4
    for (int i = tid; i < NF * 40; i += NTHR) sF[i] = 0.f;
    __syncthreads();
    for (int i = tid; i < NF * 25; i += NTHR) {
        int fi = i / 25, r25 = i - fi * 25;
        int ky = r25 / 5, kx = r25 - ky * 5;
        sF[fi * 40 + ky * 8 + kx] = filt[i];
    }
    for (int i = tid; i < UT * UT; i += NTHR) {           // 1600 logical cells
        int r = i / UT, c = i - r * UT;
        int gy = oy0 - 4 + r, gx = ox0 - 4 + c;
        float v = 0.f;
        if ((unsigned)gy < IMH && (unsigned)gx < IMW) v = ub[gy * IMW + gx];
        sU[r * SRS + c] = v;
    }
    __syncthreads();

    const float invM = s_invM;

    // ---- u_sigma/M on phi tile; zero outside image ----
    for (int i = tid; i < PT * PT; i += NTHR) {
        int r = i / PT, c = i - r * PT;
        int gy = oy0 - 2 + r, gx = ox0 - 2 + c;
        float v = 0.f;
        if ((unsigned)gy < IMH && (unsigned)gx < IMW) {
            float s0 = sU[(r + 1) * SRS + c + 1] + sU[(r + 1) * SRS + c + 2] + sU[(r + 1) * SRS + c + 3];
            float s1 = sU[(r + 2) * SRS + c + 1] + sU[(r + 2) * SRS + c + 2] + sU[(r + 2) * SRS + c + 3];
            float s2 = sU[(r + 3) * SRS + c + 1] + sU[(r + 3) * SRS + c + 2] + sU[(r + 3) * SRS + c + 3];
            v = (s0 + s1 + s2) * (1.f / 9.f) * invM;
        }
        sUS[r * PRS + c] = v;
    }
    __syncthreads();

    // adjoint: 1x4 strip per thread, 256 strips cover the 32x32 tile
    const int qy  = gt >> 3;
    const int qc0 = (gt & 7) * 4;
    float acc0 = 0.f, acc1 = 0.f, acc2 = 0.f, acc3 = 0.f;

    const int fbase = g * NFG;

    #define GBAR() asm volatile("bar.sync %0, %1;" :: "r"(g + 1), "r"(256) : "memory")

    #define LUT_EVAL(CONV, USV, RES)                                          \
        {                                                                     \
            float tt = fmaf((CONV), LUT_INVH, 512.0f);                        \
            float yy = tt + MAGICF;                                           \
            int ii = __float_as_int(yy) - MAGICI;                             \
            ii = min(max(ii, 0), NCELL - 1);                                  \
            float frac = tt - (yy - MAGICF);                                  \
            float2 cell = sLUT[ii];                                           \
            RES = (USV) * fmaf(cell.y, frac, cell.x);                         \
        }

    // 20 FMAs: 1x4 outputs, 5 taps of one ky row, window (A,B)
    #define ROW_FMA(ACC, A, B, TQ, T4)                                        \
        ACC##0 = fmaf(A.x, TQ.x, ACC##0); ACC##1 = fmaf(A.y, TQ.x, ACC##1);   \
        ACC##2 = fmaf(A.z, TQ.x, ACC##2); ACC##3 = fmaf(A.w, TQ.x, ACC##3);   \
        ACC##0 = fmaf(A.y, TQ.y, ACC##0); ACC##1 = fmaf(A.z, TQ.y, ACC##1);   \
        ACC##2 = fmaf(A.w, TQ.y, ACC##2); ACC##3 = fmaf(B.x, TQ.y, ACC##3);   \
        ACC##0 = fmaf(A.z, TQ.z, ACC##0); ACC##1 = fmaf(A.w, TQ.z, ACC##1);   \
        ACC##2 = fmaf(B.x, TQ.z, ACC##2); ACC##3 = fmaf(B.y, TQ.z, ACC##3);   \
        ACC##0 = fmaf(A.w, TQ.w, ACC##0); ACC##1 = fmaf(B.x, TQ.w, ACC##1);   \
        ACC##2 = fmaf(B.y, TQ.w, ACC##2); ACC##3 = fmaf(B.z, TQ.w, ACC##3);   \
        ACC##0 = fmaf(B.x, T4, ACC##0); ACC##1 = fmaf(B.y, T4, ACC##1);       \
        ACC##2 = fmaf(B.z, T4, ACC##2); ACC##3 = fmaf(B.w, T4, ACC##3);

    // forward for a PAIR of filters: each row window feeds both tap sets
    #define FWDPAIR(FA, FB, D0, D1)                                           \
        for (int t = gt; t < 324; t += 256) {                                 \
            int r = t / 9, c0 = (t - r * 9) * 4;                              \
            float a0 = 0.f, a1 = 0.f, a2 = 0.f, a3 = 0.f;                     \
            float b0 = 0.f, b1 = 0.f, b2 = 0.f, b3 = 0.f;                     \
            _Pragma("unroll")                                                 \
            for (int ky = 0; ky < 5; ky++) {                                  \
                const float* FpA = &sF[(FA) * 40 + ky * 8];                   \
                const float* FpB = &sF[(FB) * 40 + ky * 8];                   \
                float4 tqa = *(const float4*)FpA; float ta4 = FpA[4];         \
                float4 tqb = *(const float4*)FpB; float tb4 = FpB[4];         \
                const float4* rp = (const float4*)&sU[(r + ky) * SRS + c0];   \
                float4 A = rp[0], B = rp[1];                                  \
                ROW_FMA(a, A, B, tqa, ta4)                                    \
                ROW_FMA(b, A, B, tqb, tb4)                                    \
            }                                                                 \
            float4 usv = *(const float4*)&sUS[r * PRS + c0];                  \
            float ra0, ra1, ra2, ra3, rb0, rb1, rb2, rb3;                     \
            LUT_EVAL(a0, usv.x, ra0) LUT_EVAL(a1, usv.y, ra1)                 \
            LUT_EVAL(a2, usv.z, ra2) LUT_EVAL(a3, usv.w, ra3)                 \
            LUT_EVAL(b0, usv.x, rb0) LUT_EVAL(b1, usv.y, rb1)                 \
            LUT_EVAL(b2, usv.z, rb2) LUT_EVAL(b3, usv.w, rb3)                 \
            *(float4*)&(D0)[r * PRS + c0] = make_float4(ra0, ra1, ra2, ra3);  \
            *(float4*)&(D1)[r * PRS + c0] = make_float4(rb0, rb1, rb2, rb3);  \
        }

    // adjoint for one filter from SRC buffer (taps flipped in registers)
    #define ADJ(FI, SRC)                                                      \
        {                                                                     \
            _Pragma("unroll")                                                 \
            for (int ky = 0; ky < 5; ky++) {                                  \
                const float* Fp = &sF[(FI) * 40 + (4 - ky) * 8];              \
                float4 tq0 = *(const float4*)Fp;                              \
                float  t5  = Fp[4];                                           \
                float4 trq = make_float4(t5, tq0.w, tq0.z, tq0.y);            \
                float  tr4 = tq0.x;                                           \
                const float4* rp = (const float4*)&(SRC)[(qy + ky) * PRS + qc0]; \
                float4 A = rp[0], B = rp[1];                                  \
                ROW_FMA(acc, A, B, trq, tr4)                                  \
            }                                                                 \
        }

    // ---- pipelined pair loop: 1 named barrier per pair ----
    FWDPAIR(fbase + 0, fbase + 1, pb0, pb1)
    GBAR();
    #pragma unroll 1
    for (int p = 1; p < NFG / 2; p++) {
        if (p & 1) { FWDPAIR(fbase + 2 * p, fbase + 2 * p + 1, pb2, pb3) }
        else       { FWDPAIR(fbase + 2 * p, fbase + 2 * p + 1, pb0, pb1) }
        if ((p - 1) & 1) { ADJ(fbase + 2 * p - 2, pb2) ADJ(fbase + 2 * p - 1, pb3) }
        else             { ADJ(fbase + 2 * p - 2, pb0) ADJ(fbase + 2 * p - 1, pb1) }
        GBAR();
    }
    {   // final pair: NFG/2-1 = 5 -> wrote pb2/pb3
        ADJ(fbase + NFG - 2, pb2)
        ADJ(fbase + NFG - 1, pb3)
    }
    #undef FWDPAIR
    #undef ADJ
    #undef ROW_FMA
    #undef LUT_EVAL
    #undef GBAR

    // ---- combine group accumulators (group 1 -> smem; group 0 sums) ----
    __syncthreads();
    if (g == 1) {
        float4* buf = (float4*)(smem + OFF_PHI);      // group0's pb0 region
        buf[gt] = make_float4(acc0, acc1, acc2, acc3);
    }
    __syncthreads();

    // ---- epilogue: reaction + clip (group 0) ----
    if (g == 0) {
        float4 c0 = ((const float4*)(smem + OFF_PHI))[gt];
        acc0 += c0.x; acc1 += c0.y; acc2 += c0.z; acc3 += c0.w;
        const float lambda = lam[0];
        const int gy = oy0 + qy;
        if (gy < IMH) {
            float accs[4] = {acc0, acc1, acc2, acc3};
            float4 uv4 = *(const float4*)&sU[(qy + 4) * SRS + qc0 + 4];
            float uvs[4] = {uv4.x, uv4.y, uv4.z, uv4.w};
            #pragma unroll
            for (int k = 0; k < 4; k++) {
                int gx = ox0 + qc0 + k;
                if (gx < IMW) {
                    float uv = uvs[k];
                    float fv = fb[gy * IMW + gx];
                    float reac = lambda * (uv - fv) / (uv * uv + 1e-3f);
                    float o = uv - accs[k] - reac;
                    o = fminf(fmaxf(o, 0.f), 1.f);
                    ob[gy * IMW + gx] = o;
                }
            }
        }
    }
}

// ---------------------------------------------------------------------------
// Launch
// ---------------------------------------------------------------------------
extern "C" void kernel_launch(void* const* d_in, const int* in_sizes, int n_in,
                              void* d_out, int out_size) {
    const float* u    = (const float*)d_in[0];
    const float* f    = (const float*)d_in[1];
    const float* filt = (const float*)d_in[2];
    const float* lam  = (const float*)d_in[3];
    const float* mu   = (const float*)d_in[4];
    const float* wts  = (const float*)d_in[5];
    float* out = (float*)d_out;

    // SMEM_BYTES > 48KB needs the opt-in attribute. Set once, outside graph
    // capture (the harness's correctness call precedes capture).
    static bool attr_set = false;
    if (!attr_set) {
        cudaFuncSetAttribute(k_main, cudaFuncAttributeMaxDynamicSharedMemorySize,
                             SMEM_BYTES);
        attr_set = true;
    }

    k_init<<<68, 256>>>(u, mu, wts);
    dim3 grid((IMW + TILE - 1) / TILE, (IMH + TILE - 1) / TILE, BATCH);
    k_main<<<grid, NTHR, SMEM_BYTES>>>(u, f, filt, lam, out);
}

// round 14
// speedup vs baseline: 1.1704x; 1.0625x over previous
#include <cuda_runtime.h>

// Problem constants
#define BATCH 8
#define IMH 180
#define IMW 180
#define NF 24
#define NB 31
#define NPIX (IMH * IMW)          // 32400
#define NTOT (BATCH * NPIX)       // 259200
#define N4   (NTOT / 4)           // 64800

#define TILE 32
#define UT 40                      // u tile rows (TILE + 2*4)
#define PT 36                      // phi tile rows (TILE + 2*2)
#define RS 44                      // padded row stride (words): conflict-free phases

// LUT for phi(x); nearest-knot + centered slope, magic-number index
#define NCELL 1024
#define XMIN (-2.0f)
#define XMAX (2.0f)
#define LUT_H ((XMAX - XMIN) / (float)NCELL)
#define LUT_INVH ((float)NCELL / (XMAX - XMIN))
#define MAGICF 12582912.0f         // 1.5 * 2^23
#define MAGICI 0x4B400000

#define NTHR 512                   // 4 filter-groups of 128 threads
#define NFG  6                     // filters per group

__device__ float  g_partials[64];
__device__ float2 g_lut[NCELL];

// ---------------------------------------------------------------------------
// k_init: blocks [0,4) build the LUT (value at knot, centered slope);
// blocks [4,68) weighted partial sums for M.
// ---------------------------------------------------------------------------
__global__ void k_init(const float* __restrict__ u,
                       const float* __restrict__ mu,
                       const float* __restrict__ wts) {
    const int tid = threadIdx.x;
    if (blockIdx.x < 4) {
        int i = blockIdx.x * 256 + tid;        // 0..1023
        float xc = XMIN + (float)i * LUT_H;
        float pm = 0.f, p0 = 0.f, pp = 0.f;
        #pragma unroll 1
        for (int j = 0; j < NB; j++) {
            float m = mu[j], w = wts[j];
            float dm = xc - LUT_H - m, d0 = xc - m, dp = xc + LUT_H - m;
            pm += w * expf(-50.f * dm * dm);
            p0 += w * expf(-50.f * d0 * d0);
            pp += w * expf(-50.f * dp * dp);
        }
        g_lut[i] = make_float2(p0, 0.5f * (pp - pm));
    } else {
        __shared__ float sm[256];
        const int pb = blockIdx.x - 4;         // 0..63
        float s = 0.f;
        for (int i = pb * 256 + tid; i < N4; i += 64 * 256) {
            int idx4 = i * 4;
            int p = idx4 % NPIX;
            int y = p / IMW;
            int x0 = p - y * IMW;
            float wy = 3.f - (y == 0 ? 1.f : 0.f) - (y == IMH - 1 ? 1.f : 0.f);
            float4 v = ((const float4*)u)[i];
            float w0 = (x0 == 0) ? 2.f : 3.f;
            float w3 = (x0 == IMW - 4) ? 2.f : 3.f;
            s += wy * (v.x * w0 + v.y * 3.f + v.z * 3.f + v.w * w3);
        }
        sm[tid] = s;
        __syncthreads();
        for (int o = 128; o > 0; o >>= 1) {
            if (tid < o) sm[tid] += sm[tid + o];
            __syncthreads();
        }
        if (tid == 0) g_partials[pb] = sm[0];
    }
}

// ---------------------------------------------------------------------------
// k_main: fused TNRD stage per 32x32 tile; 4 filter-groups of 128 threads,
// double-buffered phi, 1 named barrier per filter. All 2-D smem tiles use a
// padded 44-word row stride so every LDS.128/STS.128 phase is bank-disjoint.
// Dynamic smem layout (bytes):
//   [0, 8192)        sLUT  : 1024 x float2
//   [8192, 15232)    sU    : 40 rows x 44 stride
//   [15232, 21568)   sUS   : 36 rows x 44 stride (u_sigma/M, 0 outside image)
//   [21568, 72256)   sPhi  : 8 buffers of 36 rows x 44 stride (2 per group)
//   [72256, 76096)   sF    : 24 filters x 5 rows x 8 floats (padded)
// ---------------------------------------------------------------------------
#define OFF_LUT 0
#define OFF_U   8192
#define OFF_US  15232
#define OFF_PHI 21568
#define OFF_F   72256
#define PHI_STRIDE (PT * RS * 4)   // 6336 bytes
#define SMEM_BYTES 76096

__global__ __launch_bounds__(NTHR, 2) void k_main(
    const float* __restrict__ u,
    const float* __restrict__ f,
    const float* __restrict__ filt,
    const float* __restrict__ lam,
    float* __restrict__ out)
{
    extern __shared__ char smem[];
    float2* sLUT = (float2*)(smem + OFF_LUT);
    float*  sU   = (float*)(smem + OFF_U);
    float*  sUS  = (float*)(smem + OFF_US);
    float*  sF   = (float*)(smem + OFF_F);
    __shared__ float s_invM;

    const int b   = blockIdx.z;
    const int oy0 = blockIdx.y * TILE;
    const int ox0 = blockIdx.x * TILE;
    const int tid = threadIdx.x;
    const int g   = tid >> 7;          // filter-group 0..3
    const int gt  = tid & 127;         // lane within group

    const float* ub = u + b * NPIX;
    const float* fb = f + b * NPIX;
    float* ob = out + b * NPIX;

    float* phiBuf[2] = { (float*)(smem + OFF_PHI + (2 * g + 0) * PHI_STRIDE),
                         (float*)(smem + OFF_PHI + (2 * g + 1) * PHI_STRIDE) };

    // ---- invM: single-warp shuffle reduction over 64 partials ----
    if (tid < 32) {
        float s = g_partials[tid] + g_partials[tid + 32];
        #pragma unroll
        for (int o = 16; o > 0; o >>= 1)
            s += __shfl_down_sync(0xffffffffu, s, o);
        if (tid == 0)
            s_invM = 1.f / (s / (9.f * (float)NTOT) + 0.001f);
    }

    // ---- cooperative loads ----
    {
        const float4* lg = (const float4*)g_lut;
        float4* ls = (float4*)sLUT;
        ls[tid] = lg[tid];                         // 512 float4 = whole LUT
    }
    for (int i = tid; i < NF * 40; i += NTHR) sF[i] = 0.f;   // pad lanes
    __syncthreads();
    for (int i = tid; i < NF * 25; i += NTHR) {
        int fi = i / 25, r25 = i - fi * 25;
        int ky = r25 / 5, kx = r25 - ky * 5;
        sF[fi * 40 + ky * 8 + kx] = filt[i];
    }
    for (int i = tid; i < UT * UT; i += NTHR) {    // 1600 logical u cells
        int r = i / UT, c = i - r * UT;
        int gy = oy0 - 4 + r, gx = ox0 - 4 + c;
        float v = 0.f;
        if ((unsigned)gy < IMH && (unsigned)gx < IMW) v = ub[gy * IMW + gx];
        sU[r * RS + c] = v;
    }
    __syncthreads();

    const float invM = s_invM;

    // ---- u_sigma/M on phi tile; zero outside image ----
    for (int i = tid; i < PT * PT; i += NTHR) {
        int r = i / PT, c = i - r * PT;
        int gy = oy0 - 2 + r, gx = ox0 - 2 + c;
        float v = 0.f;
        if ((unsigned)gy < IMH && (unsigned)gx < IMW) {
            float s0 = sU[(r + 1) * RS + c + 1] + sU[(r + 1) * RS + c + 2] + sU[(r + 1) * RS + c + 3];
            float s1 = sU[(r + 2) * RS + c + 1] + sU[(r + 2) * RS + c + 2] + sU[(r + 2) * RS + c + 3];
            float s2 = sU[(r + 3) * RS + c + 1] + sU[(r + 3) * RS + c + 2] + sU[(r + 3) * RS + c + 3];
            v = (s0 + s1 + s2) * (1.f / 9.f) * invM;
        }
        sUS[r * RS + c] = v;
    }
    __syncthreads();

    // ---- per-thread fixed strips ----
    const int ffr0 = (gt / 9) * 3;        // forward: 3x4 strip, 108 active
    const int ffc0 = (gt % 9) * 4;
    const bool fwd_on = (gt < 108);
    const int qr0 = (gt >> 3) * 2;        // adjoint: 2x4 strip, 128 active
    const int qc0 = (gt & 7) * 4;

    float acc[8];
    #pragma unroll
    for (int k = 0; k < 8; k++) acc[k] = 0.f;

    const int fbase = g * NFG;

    #define GBAR() asm volatile("bar.sync %0, %1;" :: "r"(g + 1), "r"(128) : "memory")

    // ---- forward: 5x5 conv (ky-major, vector taps) + magic-LUT phi + scale ----
    #define FWD(FI, DST)                                                      \
        if (fwd_on) {                                                         \
            const float* Fp = &sF[(FI) * 40];                                 \
            float a[12];                                                      \
            _Pragma("unroll")                                                 \
            for (int k = 0; k < 12; k++) a[k] = 0.f;                          \
            _Pragma("unroll")                                                 \
            for (int ky = 0; ky < 5; ky++) {                                  \
                float4 tq = *(const float4*)&Fp[ky * 8];                      \
                float t4v = Fp[ky * 8 + 4];                                   \
                _Pragma("unroll")                                             \
                for (int rr = 0; rr < 3; rr++) {                              \
                    const float4* rp = (const float4*)&sU[(ffr0 + rr + ky) * RS + ffc0]; \
                    float4 A = rp[0], B = rp[1];                              \
                    a[rr*4+0] = fmaf(A.x, tq.x, a[rr*4+0]); a[rr*4+1] = fmaf(A.y, tq.x, a[rr*4+1]); \
                    a[rr*4+2] = fmaf(A.z, tq.x, a[rr*4+2]); a[rr*4+3] = fmaf(A.w, tq.x, a[rr*4+3]); \
                    a[rr*4+0] = fmaf(A.y, tq.y, a[rr*4+0]); a[rr*4+1] = fmaf(A.z, tq.y, a[rr*4+1]); \
                    a[rr*4+2] = fmaf(A.w, tq.y, a[rr*4+2]); a[rr*4+3] = fmaf(B.x, tq.y, a[rr*4+3]); \
                    a[rr*4+0] = fmaf(A.z, tq.z, a[rr*4+0]); a[rr*4+1] = fmaf(A.w, tq.z, a[rr*4+1]); \
                    a[rr*4+2] = fmaf(B.x, tq.z, a[rr*4+2]); a[rr*4+3] = fmaf(B.y, tq.z, a[rr*4+3]); \
                    a[rr*4+0] = fmaf(A.w, tq.w, a[rr*4+0]); a[rr*4+1] = fmaf(B.x, tq.w, a[rr*4+1]); \
                    a[rr*4+2] = fmaf(B.y, tq.w, a[rr*4+2]); a[rr*4+3] = fmaf(B.z, tq.w, a[rr*4+3]); \
                    a[rr*4+0] = fmaf(B.x, t4v, a[rr*4+0]); a[rr*4+1] = fmaf(B.y, t4v, a[rr*4+1]); \
                    a[rr*4+2] = fmaf(B.z, t4v, a[rr*4+2]); a[rr*4+3] = fmaf(B.w, t4v, a[rr*4+3]); \
                }                                                             \
            }                                                                 \
            _Pragma("unroll")                                                 \
            for (int rr = 0; rr < 3; rr++) {                                  \
                float4 usv = *(const float4*)&sUS[(ffr0 + rr) * RS + ffc0];   \
                float us[4] = {usv.x, usv.y, usv.z, usv.w};                   \
                float res[4];                                                 \
                _Pragma("unroll")                                             \
                for (int k = 0; k < 4; k++) {                                 \
                    float tt = fmaf(a[rr * 4 + k], LUT_INVH, 512.0f);         \
                    float yy = tt + MAGICF;                                   \
                    int ii = __float_as_int(yy) - MAGICI;                     \
                    ii = min(max(ii, 0), NCELL - 1);                          \
                    float frac = tt - (yy - MAGICF);                          \
                    float2 cell = sLUT[ii];                                   \
                    res[k] = us[k] * fmaf(cell.y, frac, cell.x);              \
                }                                                             \
                *(float4*)&(DST)[(ffr0 + rr) * RS + ffc0] =                   \
                    make_float4(res[0], res[1], res[2], res[3]);              \
            }                                                                 \
        }

    // ---- adjoint: flipped 5x5 conv; taps reversed in registers ----
    #define ADJ(FI, SRC)                                                      \
        {                                                                     \
            const float* Fp = &sF[(FI) * 40];                                 \
            float a[8];                                                       \
            _Pragma("unroll")                                                 \
            for (int k = 0; k < 8; k++) a[k] = 0.f;                           \
            _Pragma("unroll")                                                 \
            for (int ky = 0; ky < 5; ky++) {                                  \
                float4 tq = *(const float4*)&Fp[(4 - ky) * 8];                \
                float tr0 = Fp[(4 - ky) * 8 + 4];                             \
                float tr1 = tq.w, tr2 = tq.z, tr3 = tq.y, tr4 = tq.x;         \
                _Pragma("unroll")                                             \
                for (int rr = 0; rr < 2; rr++) {                              \
                    const float4* rp = (const float4*)&(SRC)[(qr0 + rr + ky) * RS + qc0]; \
                    float4 A = rp[0], B = rp[1];                              \
                    a[rr*4+0] = fmaf(A.x, tr0, a[rr*4+0]); a[rr*4+1] = fmaf(A.y, tr0, a[rr*4+1]); \
                    a[rr*4+2] = fmaf(A.z, tr0, a[rr*4+2]); a[rr*4+3] = fmaf(A.w, tr0, a[rr*4+3]); \
                    a[rr*4+0] = fmaf(A.y, tr1, a[rr*4+0]); a[rr*4+1] = fmaf(A.z, tr1, a[rr*4+1]); \
                    a[rr*4+2] = fmaf(A.w, tr1, a[rr*4+2]); a[rr*4+3] = fmaf(B.x, tr1, a[rr*4+3]); \
                    a[rr*4+0] = fmaf(A.z, tr2, a[rr*4+0]); a[rr*4+1] = fmaf(A.w, tr2, a[rr*4+1]); \
                    a[rr*4+2] = fmaf(B.x, tr2, a[rr*4+2]); a[rr*4+3] = fmaf(B.y, tr2, a[rr*4+3]); \
                    a[rr*4+0] = fmaf(A.w, tr3, a[rr*4+0]); a[rr*4+1] = fmaf(B.x, tr3, a[rr*4+1]); \
                    a[rr*4+2] = fmaf(B.y, tr3, a[rr*4+2]); a[rr*4+3] = fmaf(B.z, tr3, a[rr*4+3]); \
                    a[rr*4+0] = fmaf(B.x, tr4, a[rr*4+0]); a[rr*4+1] = fmaf(B.y, tr4, a[rr*4+1]); \
                    a[rr*4+2] = fmaf(B.z, tr4, a[rr*4+2]); a[rr*4+3] = fmaf(B.w, tr4, a[rr*4+3]); \
                }                                                             \
            }                                                                 \
            _Pragma("unroll")                                                 \
            for (int k = 0; k < 8; k++) acc[k] += a[k];                       \
        }

    // ---- pipelined loop: 1 named barrier per filter ----
    FWD(fbase + 0, phiBuf[0])
    GBAR();
    #pragma unroll 1
    for (int kf = 1; kf < NFG; kf++) {
        FWD(fbase + kf, phiBuf[kf & 1])
        ADJ(fbase + kf - 1, phiBuf[(kf - 1) & 1])
        GBAR();
    }
    ADJ(fbase + NFG - 1, phiBuf[(NFG - 1) & 1])
    #undef FWD
    #undef ADJ
    #undef GBAR

    // ---- combine group accumulators (groups 1..3 -> smem; group 0 sums) ----
    __syncthreads();                 // all groups done with their phi buffers
    if (g > 0) {
        float4* buf = (float4*)(smem + OFF_PHI + (2 * g) * PHI_STRIDE);
        buf[gt * 2 + 0] = make_float4(acc[0], acc[1], acc[2], acc[3]);
        buf[gt * 2 + 1] = make_float4(acc[4], acc[5], acc[6], acc[7]);
    }
    __syncthreads();

    // ---- epilogue: reaction + clip (group 0) ----
    if (g == 0) {
        #pragma unroll
        for (int gg = 1; gg < 4; gg++) {
            const float4* buf = (const float4*)(smem + OFF_PHI + (2 * gg) * PHI_STRIDE);
            float4 c0 = buf[gt * 2 + 0], c1 = buf[gt * 2 + 1];
            acc[0] += c0.x; acc[1] += c0.y; acc[2] += c0.z; acc[3] += c0.w;
            acc[4] += c1.x; acc[5] += c1.y; acc[6] += c1.z; acc[7] += c1.w;
        }
        const float lambda = lam[0];
        #pragma unroll
        for (int rr = 0; rr < 2; rr++) {
            const int gy = oy0 + qr0 + rr;
            if (gy < IMH) {
                float4 uv4 = *(const float4*)&sU[(qr0 + rr + 4) * RS + qc0 + 4];
                float uvs[4] = {uv4.x, uv4.y, uv4.z, uv4.w};
                #pragma unroll
                for (int k = 0; k < 4; k++) {
                    int gx = ox0 + qc0 + k;
                    if (gx < IMW) {
                        float uv = uvs[k];
                        float fv = fb[gy * IMW + gx];
                        float reac = lambda * (uv - fv) / (uv * uv + 1e-3f);
                        float o = uv - acc[rr * 4 + k] - reac;
                        o = fminf(fmaxf(o, 0.f), 1.f);
                        ob[gy * IMW + gx] = o;
                    }
                }
            }
        }
    }
}

// ---------------------------------------------------------------------------
// Launch
// ---------------------------------------------------------------------------
extern "C" void kernel_launch(void* const* d_in, const int* in_sizes, int n_in,
                              void* d_out, int out_size) {
    const float* u    = (const float*)d_in[0];
    const float* f    = (const float*)d_in[1];
    const float* filt = (const float*)d_in[2];
    const float* lam  = (const float*)d_in[3];
    const float* mu   = (const float*)d_in[4];
    const float* wts  = (const float*)d_in[5];
    float* out = (float*)d_out;

    // SMEM_BYTES > 48KB needs the opt-in attribute. Set once, outside graph
    // capture (the harness's correctness call precedes capture).
    static bool attr_set = false;
    if (!attr_set) {
        cudaFuncSetAttribute(k_main, cudaFuncAttributeMaxDynamicSharedMemorySize,
                             SMEM_BYTES);
        attr_set = true;
    }

    k_init<<<68, 256>>>(u, mu, wts);
    dim3 grid((IMW + TILE - 1) / TILE, (IMH + TILE - 1) / TILE, BATCH);
    k_main<<<grid, NTHR, SMEM_BYTES>>>(u, f, filt, lam, out);
}